// round 2
// baseline (speedup 1.0000x reference)
#include <cuda_runtime.h>

// 64-pt inverse DFT split across 4 threads: per-thread 16-pt (radix-4x4),
// twiddle, then cross-lane radix-4 via shfl_xor. 32 batches per 128-thread
// block; smem staging for fully coalesced global traffic.

#define NT     128            // threads per block
#define NB     32             // batches per block (NT/4)
#define ROWF   132            // padded row stride in floats (128 data + 4 pad)
#define TWOFF  (NB * ROWF)    // twiddle table offset (floats)
#define SMEMF  (TWOFF + 92)   // 46 float2 twiddles

__global__ void __launch_bounds__(NT, 5)
ofdm_ifft64_kernel(const float4* __restrict__ gin, float4* __restrict__ gout) {
    __shared__ float smem[SMEMF];
    const int tid = threadIdx.x;
    const int bid = blockIdx.x;
    const int t   = tid & 3;        // lane within 4-thread group
    const int bl  = tid >> 2;       // batch-local index (row)

    // Twiddle table: T(p) = e^{+j pi p / 32} / 64, p = n1*t in [0, 45]
    if (tid < 46) {
        float s, c;
        sincospif((float)tid * (1.0f / 32.0f), &s, &c);
        ((float2*)(smem + TWOFF))[tid] = make_float2(c * 0.015625f, s * 0.015625f);
    }

    // Coalesced global -> smem staging (32 rows x 32 float4)
    const float4* src = gin + (size_t)bid * (NB * 32);
    #pragma unroll
    for (int i = 0; i < 8; i++) {
        int idx = tid + i * NT;
        int row = idx >> 5, col = idx & 31;
        *(float4*)(smem + row * ROWF + col * 4) = src[idx];
    }
    __syncthreads();

    // Load my 16 complex samples: x[4*k1 + t]  (conflict-free scalar LDS)
    float* myrow = smem + bl * ROWF;
    float ur[16], ui[16];
    #pragma unroll
    for (int k1 = 0; k1 < 16; k1++) {
        ur[k1] = myrow[4 * k1 + t];
        ui[k1] = myrow[64 + 4 * k1 + t];
    }

    // Pilot overrides: k=11 -> (t=3,k1=2), 25 -> (1,6), 39 -> (3,9), 53 -> (1,13)
    if (t == 3) { ur[2] = 1.0f; ui[2] = 0.0f; ur[9]  = 1.0f; ui[9]  = 0.0f; }
    if (t == 1) { ur[6] = 1.0f; ui[6] = 0.0f; ur[13] = 1.0f; ui[13] = 0.0f; }

    // ---- 16-pt IDFT (positive exponent), radix-4 DIT ----
    // Stage 1: for each q, 4-pt over p on elements {q, q+4, q+8, q+12};
    // result G_q[m0] stored at index 4*m0 + q, fused with twiddle e^{j2pi m0 q/16}.
    const float W16R[10] = { 1.0f, 0.92387953251f, 0.70710678119f, 0.38268343236f,
                             0.0f, 0.0f, -0.70710678119f, 0.0f, 0.0f, -0.92387953251f };
    const float W16I[10] = { 0.0f, 0.38268343236f, 0.70710678119f, 0.92387953251f,
                             1.0f, 0.0f,  0.70710678119f, 0.0f, 0.0f, -0.38268343236f };
    #pragma unroll
    for (int q = 0; q < 4; q++) {
        float ar = ur[q],      ai = ui[q];
        float br = ur[q + 4],  bi = ui[q + 4];
        float cr = ur[q + 8],  ci = ui[q + 8];
        float dr = ur[q + 12], di = ui[q + 12];
        float s0r = ar + cr, s0i = ai + ci, s1r = ar - cr, s1i = ai - ci;
        float s2r = br + dr, s2i = bi + di, s3r = br - dr, s3i = bi - di;
        float g0r = s0r + s2r, g0i = s0i + s2i;      // m0=0
        float g1r = s1r - s3i, g1i = s1i + s3r;      // m0=1: s1 + j*s3
        float g2r = s0r - s2r, g2i = s0i - s2i;      // m0=2
        float g3r = s1r + s3i, g3i = s1i - s3r;      // m0=3: s1 - j*s3
        // Twiddle by e^{j2pi m0 q / 16}, write to 4*m0 + q
        ur[q]      = g0r;  ui[q]      = g0i;
        { const float wr = W16R[q],   wi = W16I[q];
          ur[q + 4]  = g1r * wr - g1i * wi;  ui[q + 4]  = g1r * wi + g1i * wr; }
        { const float wr = W16R[2*q], wi = W16I[2*q];
          ur[q + 8]  = g2r * wr - g2i * wi;  ui[q + 8]  = g2r * wi + g2i * wr; }
        { const float wr = W16R[3*q], wi = W16I[3*q];
          ur[q + 12] = g3r * wr - g3i * wi;  ui[q + 12] = g3r * wi + g3i * wr; }
    }

    // Stage 2: for each m0, 4-pt over q on contiguous elements {4m0..4m0+3};
    // Y[m0 + 4*m1], then Z twiddle e^{j pi n1 t / 32}/64 (n1 = m0 + 4*m1).
    const float2* tw = (const float2*)(smem + TWOFF);
    float yr[16], yi[16];
    #pragma unroll
    for (int m0 = 0; m0 < 4; m0++) {
        float ar = ur[4*m0],     ai = ui[4*m0];
        float br = ur[4*m0 + 1], bi = ui[4*m0 + 1];
        float cr = ur[4*m0 + 2], ci = ui[4*m0 + 2];
        float dr = ur[4*m0 + 3], di = ui[4*m0 + 3];
        float s0r = ar + cr, s0i = ai + ci, s1r = ar - cr, s1i = ai - ci;
        float s2r = br + dr, s2i = bi + di, s3r = br - dr, s3i = bi - di;
        float y0r = s0r + s2r, y0i = s0i + s2i;
        float y1r = s1r - s3i, y1i = s1i + s3r;
        float y2r = s0r - s2r, y2i = s0i - s2i;
        float y3r = s1r + s3i, y3i = s1i - s3r;
        #pragma unroll
        for (int m1 = 0; m1 < 4; m1++) {
            int n1 = m0 + 4 * m1;
            float vr = (m1 == 0) ? y0r : (m1 == 1) ? y1r : (m1 == 2) ? y2r : y3r;
            float vi = (m1 == 0) ? y0i : (m1 == 1) ? y1i : (m1 == 2) ? y2i : y3i;
            float2 w = tw[n1 * t];
            yr[n1] = vr * w.x - vi * w.y;
            yi[n1] = vr * w.y + vi * w.x;
        }
    }

    // ---- Cross-lane radix-4 over t: X[n1 + 16*n2] = sum_t Z_t j^{n2 t} ----
    const int  b    = (t >> 1) & 1;
    const int  t0   = t & 1;
    const int  n2   = b + 2 * t0;      // output block owned by this lane
    float or16[16], oi16[16];
    #pragma unroll
    for (int n1 = 0; n1 < 16; n1++) {
        float pr = __shfl_xor_sync(0xffffffffu, yr[n1], 2);
        float pi = __shfl_xor_sync(0xffffffffu, yi[n1], 2);
        float cr_ = (t & 2) ? (pr - yr[n1]) : (yr[n1] + pr);
        float ci_ = (t & 2) ? (pi - yi[n1]) : (yi[n1] + pi);
        float qr = __shfl_xor_sync(0xffffffffu, cr_, 1);
        float qi = __shfl_xor_sync(0xffffffffu, ci_, 1);
        float c0r = t0 ? qr : cr_, c0i = t0 ? qi : ci_;
        float c1r = t0 ? cr_ : qr, c1i = t0 ? ci_ : qi;
        float dr_ = b ? -c1i : c1r;     // j^b * C1
        float di_ = b ?  c1r : c1i;
        or16[n1] = t0 ? (c0r - dr_) : (c0r + dr_);
        oi16[n1] = t0 ? (c0i - di_) : (c0i + di_);
    }

    // Write my contiguous 16-output block into smem row (vectorized)
    float* obase_r = myrow + 16 * n2;
    float* obase_i = myrow + 64 + 16 * n2;
    #pragma unroll
    for (int i = 0; i < 4; i++) {
        *(float4*)(obase_r + 4 * i) = make_float4(or16[4*i], or16[4*i+1], or16[4*i+2], or16[4*i+3]);
        *(float4*)(obase_i + 4 * i) = make_float4(oi16[4*i], oi16[4*i+1], oi16[4*i+2], oi16[4*i+3]);
    }
    __syncthreads();

    // Coalesced smem -> global store
    float4* dst = gout + (size_t)bid * (NB * 32);
    #pragma unroll
    for (int i = 0; i < 8; i++) {
        int idx = tid + i * NT;
        int row = idx >> 5, col = idx & 31;
        dst[idx] = *(const float4*)(smem + row * ROWF + col * 4);
    }
}

extern "C" void kernel_launch(void* const* d_in, const int* in_sizes, int n_in,
                              void* d_out, int out_size) {
    const float4* gin = (const float4*)d_in[0];   // eq_freq [B,2,64] f32
    float4* gout = (float4*)d_out;                // out      [B,2,64] f32
    int batches = in_sizes[0] / 128;              // 262144
    int grid = batches / NB;                      // 8192
    ofdm_ifft64_kernel<<<grid, NT>>>(gin, gout);
}

// round 4
// speedup vs baseline: 1.0570x; 1.0570x over previous
#include <cuda_runtime.h>
#include <cstdint>

// 64-pt inverse DFT, 1 thread per batch (radix 8x8, register-resident).
// 1-warp CTAs process 4 tiles of 32 batches each, with double-buffered
// shared-memory staging filled by cp.async so global reads for tile g+2
// overlap compute of tile g. All sync is warp-level.

#define NT     32             // threads per block (one warp)
#define NB     32             // batches per tile
#define ROWF   132            // padded row stride in floats (128 data + 4 pad)
#define TILEF  (NB * ROWF)    // floats per tile buffer (4224)
#define TWOFF  (2 * TILEF)    // twiddle table offset
#define SMEMF  (TWOFF + 104)  // + 50 float2 twiddles (p = n1*k2 in [0,49]) + pad
#define TT     4              // tiles per CTA

__device__ __forceinline__ uint32_t sptr(const void* p) {
    return (uint32_t)__cvta_generic_to_shared(p);
}

// Async-copy one 16KB tile (32 batches x 128 floats) into a padded smem buffer.
// Chunk idx = tid + 32*i -> smem row i, col tid. Source fully coalesced.
__device__ __forceinline__ void tile_copy(float* buf, const float4* __restrict__ src, int tid) {
    #pragma unroll
    for (int i = 0; i < 32; i++) {
        uint32_t dst = sptr(buf + i * ROWF + 4 * tid);
        asm volatile("cp.async.cg.shared.global [%0], [%1], 16;\n"
                     :: "r"(dst), "l"(src + tid + 32 * i) : "memory");
    }
}

__device__ __forceinline__ void ifft8(float* tr, float* ti) {
    // 8-point DFT with POSITIVE exponent
    float e0r = tr[0] + tr[4], e0i = ti[0] + ti[4];
    float e1r = tr[0] - tr[4], e1i = ti[0] - ti[4];
    float e2r = tr[2] + tr[6], e2i = ti[2] + ti[6];
    float e3r = tr[2] - tr[6], e3i = ti[2] - ti[6];
    float E0r = e0r + e2r,  E0i = e0i + e2i;
    float E2r = e0r - e2r,  E2i = e0i - e2i;
    float E1r = e1r - e3i,  E1i = e1i + e3r;
    float E3r = e1r + e3i,  E3i = e1i - e3r;

    float o0r = tr[1] + tr[5], o0i = ti[1] + ti[5];
    float o1r = tr[1] - tr[5], o1i = ti[1] - ti[5];
    float o2r = tr[3] + tr[7], o2i = ti[3] + ti[7];
    float o3r = tr[3] - tr[7], o3i = ti[3] - ti[7];
    float O0r = o0r + o2r,  O0i = o0i + o2i;
    float O2r = o0r - o2r,  O2i = o0i - o2i;
    float O1r = o1r - o3i,  O1i = o1i + o3r;
    float O3r = o1r + o3i,  O3i = o1i - o3r;

    const float R = 0.70710678118654752f;
    float t1r =  R * (O1r - O1i), t1i =  R * (O1r + O1i);
    float t2r = -O2i,             t2i =  O2r;
    float t3r = -R * (O3r + O3i), t3i =  R * (O3r - O3i);

    tr[0] = E0r + O0r;  ti[0] = E0i + O0i;
    tr[4] = E0r - O0r;  ti[4] = E0i - O0i;
    tr[1] = E1r + t1r;  ti[1] = E1i + t1i;
    tr[5] = E1r - t1r;  ti[5] = E1i - t1i;
    tr[2] = E2r + t2r;  ti[2] = E2i + t2i;
    tr[6] = E2r - t2r;  ti[6] = E2i - t2i;
    tr[3] = E3r + t3r;  ti[3] = E3i + t3i;
    tr[7] = E3r - t3r;  ti[7] = E3i - t3i;
}

__global__ void __launch_bounds__(NT)
ofdm_ifft64_kernel(const float4* __restrict__ gin, float4* __restrict__ gout) {
    __shared__ __align__(16) float smem[SMEMF];
    const int tid = threadIdx.x;
    const long g0 = (long)blockIdx.x * TT;   // first tile index for this CTA

    // Twiddle table: T(p) = e^{+j pi p / 32} / 64, p = n1*k2 in [0,49]
    for (int p = tid; p < 50; p += NT) {
        float s, c;
        sincospif((float)p * (1.0f / 32.0f), &s, &c);
        ((float2*)(smem + TWOFF))[p] = make_float2(c * 0.015625f, s * 0.015625f);
    }

    // Prologue: prefetch tiles 0 and 1
    tile_copy(smem,         gin + g0 * (NB * 32),       tid);
    asm volatile("cp.async.commit_group;\n" ::: "memory");
    tile_copy(smem + TILEF, gin + (g0 + 1) * (NB * 32), tid);
    asm volatile("cp.async.commit_group;\n" ::: "memory");

    const float2* tw = (const float2*)(smem + TWOFF);

    for (int g = 0; g < TT; g++) {
        asm volatile("cp.async.wait_group 1;\n" ::: "memory");
        __syncwarp();

        float* buf = smem + (g & 1) * TILEF;
        float* myrow = buf + tid * ROWF;

        float xr[64], xi[64];
        #pragma unroll
        for (int i = 0; i < 16; i++) {
            float4 v = *(const float4*)(myrow + 4 * i);
            xr[4*i] = v.x; xr[4*i+1] = v.y; xr[4*i+2] = v.z; xr[4*i+3] = v.w;
        }
        #pragma unroll
        for (int i = 0; i < 16; i++) {
            float4 v = *(const float4*)(myrow + 64 + 4 * i);
            xi[4*i] = v.x; xi[4*i+1] = v.y; xi[4*i+2] = v.z; xi[4*i+3] = v.w;
        }

        // Pilot overrides
        xr[11] = 1.0f; xi[11] = 0.0f;
        xr[25] = 1.0f; xi[25] = 0.0f;
        xr[39] = 1.0f; xi[39] = 0.0f;
        xr[53] = 1.0f; xi[53] = 0.0f;

        // Stage 1: 8 IDFT-8s over k1 (stride-8), result at 8*n1+k2
        #pragma unroll
        for (int k2 = 0; k2 < 8; k2++) {
            float tr[8], ti[8];
            #pragma unroll
            for (int k1 = 0; k1 < 8; k1++) { tr[k1] = xr[8*k1 + k2]; ti[k1] = xi[8*k1 + k2]; }
            ifft8(tr, ti);
            #pragma unroll
            for (int n1 = 0; n1 < 8; n1++) { xr[8*n1 + k2] = tr[n1]; xi[8*n1 + k2] = ti[n1]; }
        }

        // Twiddle (+ 1/64 scale): element (n1,k2) *= T(n1*k2)
        #pragma unroll
        for (int n1 = 0; n1 < 8; n1++) {
            #pragma unroll
            for (int k2 = 0; k2 < 8; k2++) {
                int idx = 8*n1 + k2;
                float2 t = tw[n1 * k2];
                float a = xr[idx], b = xi[idx];
                xr[idx] = a * t.x - b * t.y;
                xi[idx] = a * t.y + b * t.x;
            }
        }

        // Stage 2: 8 IDFT-8s over k2 (contiguous), X[n1 + 8*n2]
        float yr[64], yi[64];
        #pragma unroll
        for (int n1 = 0; n1 < 8; n1++) {
            float tr[8], ti[8];
            #pragma unroll
            for (int k2 = 0; k2 < 8; k2++) { tr[k2] = xr[8*n1 + k2]; ti[k2] = xi[8*n1 + k2]; }
            ifft8(tr, ti);
            #pragma unroll
            for (int n2 = 0; n2 < 8; n2++) { yr[n1 + 8*n2] = tr[n2]; yi[n1 + 8*n2] = ti[n2]; }
        }

        // Stage outputs back into own row (only this thread touches it)
        #pragma unroll
        for (int i = 0; i < 16; i++)
            *(float4*)(myrow + 4 * i)      = make_float4(yr[4*i], yr[4*i+1], yr[4*i+2], yr[4*i+3]);
        #pragma unroll
        for (int i = 0; i < 16; i++)
            *(float4*)(myrow + 64 + 4 * i) = make_float4(yi[4*i], yi[4*i+1], yi[4*i+2], yi[4*i+3]);

        __syncwarp();

        // Coalesced smem -> global store
        float4* dst = gout + (g0 + g) * (NB * 32);
        #pragma unroll
        for (int i = 0; i < 32; i++)
            dst[tid + 32 * i] = *(const float4*)(buf + i * ROWF + 4 * tid);

        __syncwarp();

        // Refill this buffer for tile g+2 (reads above are complete)
        if (g + 2 < TT)
            tile_copy(buf, gin + (g0 + g + 2) * (NB * 32), tid);
        asm volatile("cp.async.commit_group;\n" ::: "memory");
    }
}

extern "C" void kernel_launch(void* const* d_in, const int* in_sizes, int n_in,
                              void* d_out, int out_size) {
    const float4* gin = (const float4*)d_in[0];   // eq_freq [B,2,64] f32
    float4* gout = (float4*)d_out;                // out      [B,2,64] f32
    int batches = in_sizes[0] / 128;              // 262144
    int grid = batches / (NB * TT);               // 2048
    ofdm_ifft64_kernel<<<grid, NT>>>(gin, gout);
}

// round 5
// speedup vs baseline: 1.0628x; 1.0055x over previous
#include <cuda_runtime.h>
#include <cstdint>

// 64-pt inverse DFT, 1 thread per batch (radix 8x8, register-resident).
// 1-warp CTAs, 2 tiles of 16 batches each, double-buffered cp.async staging.
// All twiddles are compile-time immediates (no smem table).

#define NT     32             // threads per block (one warp)
#define NB     16             // batches per tile
#define ROWF   132            // padded row stride in floats (128 data + 4 pad)
#define TILEF  (NB * ROWF)    // floats per tile buffer (2112)
#define SMEMF  (2 * TILEF)
#define TT     2              // tiles per CTA

// cos/sin(pi*p/32) for p = 0..49 (covers p = n1*k2, n1,k2 in [0,7])
__device__ __constant__ const float TWC[50] = {
  1.0f, 0.9951847266721969f, 0.9807852804032304f, 0.9569403357322088f,
  0.9238795325112867f, 0.8819212643483551f, 0.8314696123025452f, 0.7730104533627370f,
  0.7071067811865476f, 0.6343932841636455f, 0.5555702330196022f, 0.4713967368259976f,
  0.3826834323650898f, 0.2902846772544624f, 0.1950903220161283f, 0.0980171403295606f,
  0.0f, -0.0980171403295606f, -0.1950903220161283f, -0.2902846772544624f,
  -0.3826834323650898f, -0.4713967368259976f, -0.5555702330196022f, -0.6343932841636455f,
  -0.7071067811865476f, -0.7730104533627370f, -0.8314696123025452f, -0.8819212643483551f,
  -0.9238795325112867f, -0.9569403357322088f, -0.9807852804032304f, -0.9951847266721969f,
  -1.0f, -0.9951847266721969f, -0.9807852804032304f, -0.9569403357322088f,
  -0.9238795325112867f, -0.8819212643483551f, -0.8314696123025452f, -0.7730104533627370f,
  -0.7071067811865476f, -0.6343932841636455f, -0.5555702330196022f, -0.4713967368259976f,
  -0.3826834323650898f, -0.2902846772544624f, -0.1950903220161283f, -0.0980171403295606f,
  0.0f, 0.0980171403295606f };
__device__ __constant__ const float TWS[50] = {
  0.0f, 0.0980171403295606f, 0.1950903220161283f, 0.2902846772544624f,
  0.3826834323650898f, 0.4713967368259976f, 0.5555702330196022f, 0.6343932841636455f,
  0.7071067811865476f, 0.7730104533627370f, 0.8314696123025452f, 0.8819212643483551f,
  0.9238795325112867f, 0.9569403357322088f, 0.9807852804032304f, 0.9951847266721969f,
  1.0f, 0.9951847266721969f, 0.9807852804032304f, 0.9569403357322088f,
  0.9238795325112867f, 0.8819212643483551f, 0.8314696123025452f, 0.7730104533627370f,
  0.7071067811865476f, 0.6343932841636455f, 0.5555702330196022f, 0.4713967368259976f,
  0.3826834323650898f, 0.2902846772544624f, 0.1950903220161283f, 0.0980171403295606f,
  0.0f, -0.0980171403295606f, -0.1950903220161283f, -0.2902846772544624f,
  -0.3826834323650898f, -0.4713967368259976f, -0.5555702330196022f, -0.6343932841636455f,
  -0.7071067811865476f, -0.7730104533627370f, -0.8314696123025452f, -0.8819212643483551f,
  -0.9238795325112867f, -0.9569403357322088f, -0.9807852804032304f, -0.9951847266721969f,
  -1.0f, -0.9951847266721969f };

// Host-side mirror so the compiler can fold twiddles as immediates (indices
// are compile-time after full unroll).
#define TW_COS(p) (twc_host[p])
#define TW_SIN(p) (tws_host[p])

__device__ __forceinline__ uint32_t sptr(const void* p) {
    return (uint32_t)__cvta_generic_to_shared(p);
}

// Async-copy one 8KB tile (16 batches x 128 floats) into a padded smem buffer.
__device__ __forceinline__ void tile_copy(float* buf, const float4* __restrict__ src, int tid) {
    #pragma unroll
    for (int i = 0; i < 16; i++) {
        uint32_t dst = sptr(buf + i * ROWF + 4 * tid);
        asm volatile("cp.async.cg.shared.global [%0], [%1], 16;\n"
                     :: "r"(dst), "l"(src + tid + 32 * i) : "memory");
    }
}

__device__ __forceinline__ void ifft8(float* tr, float* ti) {
    // 8-point DFT with POSITIVE exponent
    float e0r = tr[0] + tr[4], e0i = ti[0] + ti[4];
    float e1r = tr[0] - tr[4], e1i = ti[0] - ti[4];
    float e2r = tr[2] + tr[6], e2i = ti[2] + ti[6];
    float e3r = tr[2] - tr[6], e3i = ti[2] - ti[6];
    float E0r = e0r + e2r,  E0i = e0i + e2i;
    float E2r = e0r - e2r,  E2i = e0i - e2i;
    float E1r = e1r - e3i,  E1i = e1i + e3r;
    float E3r = e1r + e3i,  E3i = e1i - e3r;

    float o0r = tr[1] + tr[5], o0i = ti[1] + ti[5];
    float o1r = tr[1] - tr[5], o1i = ti[1] - ti[5];
    float o2r = tr[3] + tr[7], o2i = ti[3] + ti[7];
    float o3r = tr[3] - tr[7], o3i = ti[3] - ti[7];
    float O0r = o0r + o2r,  O0i = o0i + o2i;
    float O2r = o0r - o2r,  O2i = o0i - o2i;
    float O1r = o1r - o3i,  O1i = o1i + o3r;
    float O3r = o1r + o3i,  O3i = o1i - o3r;

    const float R = 0.70710678118654752f;
    float t1r =  R * (O1r - O1i), t1i =  R * (O1r + O1i);
    float t2r = -O2i,             t2i =  O2r;
    float t3r = -R * (O3r + O3i), t3i =  R * (O3r - O3i);

    tr[0] = E0r + O0r;  ti[0] = E0i + O0i;
    tr[4] = E0r - O0r;  ti[4] = E0i - O0i;
    tr[1] = E1r + t1r;  ti[1] = E1i + t1i;
    tr[5] = E1r - t1r;  ti[5] = E1i - t1i;
    tr[2] = E2r + t2r;  ti[2] = E2i + t2i;
    tr[6] = E2r - t2r;  ti[6] = E2i - t2i;
    tr[3] = E3r + t3r;  ti[3] = E3i + t3i;
    tr[7] = E3r - t3r;  ti[7] = E3i - t3i;
}

__global__ void __launch_bounds__(NT)
ofdm_ifft64_kernel(const float4* __restrict__ gin, float4* __restrict__ gout) {
    // Compile-time twiddle literals (folded after full unroll): e^{j pi p/32}/64
    constexpr float twc_host[50] = {
      1.0f, 0.9951847266721969f, 0.9807852804032304f, 0.9569403357322088f,
      0.9238795325112867f, 0.8819212643483551f, 0.8314696123025452f, 0.7730104533627370f,
      0.7071067811865476f, 0.6343932841636455f, 0.5555702330196022f, 0.4713967368259976f,
      0.3826834323650898f, 0.2902846772544624f, 0.1950903220161283f, 0.0980171403295606f,
      0.0f, -0.0980171403295606f, -0.1950903220161283f, -0.2902846772544624f,
      -0.3826834323650898f, -0.4713967368259976f, -0.5555702330196022f, -0.6343932841636455f,
      -0.7071067811865476f, -0.7730104533627370f, -0.8314696123025452f, -0.8819212643483551f,
      -0.9238795325112867f, -0.9569403357322088f, -0.9807852804032304f, -0.9951847266721969f,
      -1.0f, -0.9951847266721969f, -0.9807852804032304f, -0.9569403357322088f,
      -0.9238795325112867f, -0.8819212643483551f, -0.8314696123025452f, -0.7730104533627370f,
      -0.7071067811865476f, -0.6343932841636455f, -0.5555702330196022f, -0.4713967368259976f,
      -0.3826834323650898f, -0.2902846772544624f, -0.1950903220161283f, -0.0980171403295606f,
      0.0f, 0.0980171403295606f };
    constexpr float tws_host[50] = {
      0.0f, 0.0980171403295606f, 0.1950903220161283f, 0.2902846772544624f,
      0.3826834323650898f, 0.4713967368259976f, 0.5555702330196022f, 0.6343932841636455f,
      0.7071067811865476f, 0.7730104533627370f, 0.8314696123025452f, 0.8819212643483551f,
      0.9238795325112867f, 0.9569403357322088f, 0.9807852804032304f, 0.9951847266721969f,
      1.0f, 0.9951847266721969f, 0.9807852804032304f, 0.9569403357322088f,
      0.9238795325112867f, 0.8819212643483551f, 0.8314696123025452f, 0.7730104533627370f,
      0.7071067811865476f, 0.6343932841636455f, 0.5555702330196022f, 0.4713967368259976f,
      0.3826834323650898f, 0.2902846772544624f, 0.1950903220161283f, 0.0980171403295606f,
      0.0f, -0.0980171403295606f, -0.1950903220161283f, -0.2902846772544624f,
      -0.3826834323650898f, -0.4713967368259976f, -0.5555702330196022f, -0.6343932841636455f,
      -0.7071067811865476f, -0.7730104533627370f, -0.8314696123025452f, -0.8819212643483551f,
      -0.9238795325112867f, -0.9569403357322088f, -0.9807852804032304f, -0.9951847266721969f,
      -1.0f, -0.9951847266721969f };

    __shared__ __align__(16) float smem[SMEMF];
    const int tid = threadIdx.x;
    const long g0 = (long)blockIdx.x * TT;

    // Prologue: prefetch both tiles
    tile_copy(smem,         gin + g0 * (NB * 32),       tid);
    asm volatile("cp.async.commit_group;\n" ::: "memory");
    tile_copy(smem + TILEF, gin + (g0 + 1) * (NB * 32), tid);
    asm volatile("cp.async.commit_group;\n" ::: "memory");

    #pragma unroll
    for (int g = 0; g < TT; g++) {
        if (g == 0) asm volatile("cp.async.wait_group 1;\n" ::: "memory");
        else        asm volatile("cp.async.wait_group 0;\n" ::: "memory");
        __syncwarp();

        float* buf = smem + g * TILEF;
        // Two threads share a batch? No: 32 threads, 16 batches -> threads
        // 0..15 own rows; threads 16..31 idle for compute but help copy/store.
        // Instead: each thread owns row (tid & 15); hi half-warp duplicates?
        // Simpler: all 32 threads compute, two per row would duplicate work.
        // => rows assigned to tid < 16 only.
        float xr[64], xi[64];
        float* myrow = buf + (tid & 15) * ROWF;
        #pragma unroll
        for (int i = 0; i < 16; i++) {
            float4 v = *(const float4*)(myrow + 4 * i);
            xr[4*i] = v.x; xr[4*i+1] = v.y; xr[4*i+2] = v.z; xr[4*i+3] = v.w;
        }
        #pragma unroll
        for (int i = 0; i < 16; i++) {
            float4 v = *(const float4*)(myrow + 64 + 4 * i);
            xi[4*i] = v.x; xi[4*i+1] = v.y; xi[4*i+2] = v.z; xi[4*i+3] = v.w;
        }

        if (tid < 16) {
            // Pilot overrides
            xr[11] = 1.0f; xi[11] = 0.0f;
            xr[25] = 1.0f; xi[25] = 0.0f;
            xr[39] = 1.0f; xi[39] = 0.0f;
            xr[53] = 1.0f; xi[53] = 0.0f;

            // Stage 1: 8 IDFT-8s over k1 (stride-8), result at 8*n1+k2
            #pragma unroll
            for (int k2 = 0; k2 < 8; k2++) {
                float tr[8], ti[8];
                #pragma unroll
                for (int k1 = 0; k1 < 8; k1++) { tr[k1] = xr[8*k1 + k2]; ti[k1] = xi[8*k1 + k2]; }
                ifft8(tr, ti);
                #pragma unroll
                for (int n1 = 0; n1 < 8; n1++) { xr[8*n1 + k2] = tr[n1]; xi[8*n1 + k2] = ti[n1]; }
            }

            // Twiddle (+ 1/64 scale) with compile-time constants
            #pragma unroll
            for (int n1 = 0; n1 < 8; n1++) {
                #pragma unroll
                for (int k2 = 0; k2 < 8; k2++) {
                    const int idx = 8*n1 + k2;
                    const float wr = TW_COS(n1 * k2) * 0.015625f;
                    const float wi = TW_SIN(n1 * k2) * 0.015625f;
                    float a = xr[idx], b = xi[idx];
                    xr[idx] = a * wr - b * wi;
                    xi[idx] = a * wi + b * wr;
                }
            }

            // Stage 2: 8 IDFT-8s over k2 (contiguous), X[n1 + 8*n2]
            float yr[64], yi[64];
            #pragma unroll
            for (int n1 = 0; n1 < 8; n1++) {
                float tr[8], ti[8];
                #pragma unroll
                for (int k2 = 0; k2 < 8; k2++) { tr[k2] = xr[8*n1 + k2]; ti[k2] = xi[8*n1 + k2]; }
                ifft8(tr, ti);
                #pragma unroll
                for (int n2 = 0; n2 < 8; n2++) { yr[n1 + 8*n2] = tr[n2]; yi[n1 + 8*n2] = ti[n2]; }
            }

            // Stage outputs back into own row
            #pragma unroll
            for (int i = 0; i < 16; i++)
                *(float4*)(myrow + 4 * i)      = make_float4(yr[4*i], yr[4*i+1], yr[4*i+2], yr[4*i+3]);
            #pragma unroll
            for (int i = 0; i < 16; i++)
                *(float4*)(myrow + 64 + 4 * i) = make_float4(yi[4*i], yi[4*i+1], yi[4*i+2], yi[4*i+3]);
        }
        __syncwarp();

        // Coalesced smem -> global store (all 32 threads)
        float4* dst = gout + (g0 + g) * (NB * 32);
        #pragma unroll
        for (int i = 0; i < 16; i++)
            dst[tid + 32 * i] = *(const float4*)(buf + i * ROWF + 4 * tid);
        __syncwarp();
    }
}

extern "C" void kernel_launch(void* const* d_in, const int* in_sizes, int n_in,
                              void* d_out, int out_size) {
    const float4* gin = (const float4*)d_in[0];   // eq_freq [B,2,64] f32
    float4* gout = (float4*)d_out;                // out      [B,2,64] f32
    int batches = in_sizes[0] / 128;              // 262144
    int grid = batches / (NB * TT);               // 8192
    ofdm_ifft64_kernel<<<grid, NT>>>(gin, gout);
}